// round 13
// baseline (speedup 1.0000x reference)
#include <cuda_runtime.h>
#include <cstdint>

#define NODES 207
#define HID   64
#define BATCH 64
#define BH    4096          // BATCH*HID
#define ROW   13248         // NODES*HID
#define KPAD  224
#define MPAD  256
#define MHALF 112           // nodes per cluster CTA

// ---------------- device state ----------------
__device__ float g_yA[KPAD * BH];       // y [node][bh]; rows 207..223 zero
__device__ float g_ApadT[KPAD * MPAD];  // A^T [k][m]
__device__ unsigned g_flat[256];        // per-step keys

// ---------------- threefry (partitionable) ----------------
__device__ __forceinline__ void tf2x32(unsigned k0, unsigned k1,
                                       unsigned x0, unsigned x1,
                                       unsigned &o0, unsigned &o1) {
    unsigned ks2 = k0 ^ k1 ^ 0x1BD11BDAu;
    x0 += k0; x1 += k1;
#define TFR(r) { x0 += x1; x1 = __funnelshift_l(x1, x1, (r)); x1 ^= x0; }
    TFR(13) TFR(15) TFR(26) TFR(6)
    x0 += k1;  x1 += ks2 + 1u;
    TFR(17) TFR(29) TFR(16) TFR(24)
    x0 += ks2; x1 += k0 + 2u;
    TFR(13) TFR(15) TFR(26) TFR(6)
    x0 += k0;  x1 += k1 + 3u;
    TFR(17) TFR(29) TFR(16) TFR(24)
    x0 += k1;  x1 += ks2 + 4u;
    TFR(13) TFR(15) TFR(26) TFR(6)
    x0 += ks2; x1 += k0 + 5u;
#undef TFR
    o0 = x0; o1 = x1;
}
__device__ __forceinline__ unsigned tf_bits32(unsigned k0, unsigned k1, unsigned i) {
    unsigned o0, o1;
    tf2x32(k0, k1, 0u, i, o0, o1);
    return o0 ^ o1;
}
__device__ __forceinline__ float bits_to_normal(unsigned b) {
    float f = __uint_as_float((b >> 9) | 0x3F800000u) - 1.0f;
    float u = fmaf(f, 2.0f, -0.99999994f);
    u = fmaxf(u, -0.99999994f);
    return 1.41421356f * erfinvf(u);
}

// ---------------- helpers ----------------
__device__ __forceinline__ uint32_t smem_u32(const void* p) {
    uint32_t a;
    asm("{ .reg .u64 t; cvta.to.shared.u64 t, %1; cvt.u32.u64 %0, t; }" : "=r"(a) : "l"(p));
    return a;
}
__device__ __forceinline__ void cpa16(uint32_t s, const void* g) {
    asm volatile("{ .reg .u64 ga; cvta.to.global.u64 ga, %1; "
                 "cp.async.cg.shared.global [%0], [ga], 16; }"
                 :: "r"(s), "l"(g));
}
#define CP_COMMIT() asm volatile("cp.async.commit_group;" ::: "memory")
#define CP_WAIT1()  asm volatile("cp.async.wait_group 1;" ::: "memory")
#define CP_WAIT0()  asm volatile("cp.async.wait_group 0;" ::: "memory")
#define CLUSTER_SYNC() do { \
    asm volatile("barrier.cluster.arrive.aligned;" ::: "memory"); \
    asm volatile("barrier.cluster.wait.aligned;" ::: "memory"); \
} while (0)

__device__ __forceinline__ float tf32r(float x) {
    uint32_t r;
    asm("cvt.rna.tf32.f32 %0, %1;" : "=r"(r) : "f"(x));
    return __uint_as_float(r);
}
#define MMA_TF32(acc, a, b) \
    asm volatile("mma.sync.aligned.m16n8k8.row.col.f32.tf32.tf32.f32 " \
        "{%0,%1,%2,%3}, {%4,%5,%6,%7}, {%8,%9}, {%0,%1,%2,%3};" \
        : "+f"((acc)[0]), "+f"((acc)[1]), "+f"((acc)[2]), "+f"((acc)[3]) \
        : "r"((a)[0]), "r"((a)[1]), "r"((a)[2]), "r"((a)[3]), \
          "r"((b)[0]), "r"((b)[1]))

// persistent-kernel smem layout (float indices)
#define O_Y      0                    // y [224 node][72]          = 16128
#define O_WT     16128                // Wt [64][72]               = 4608
#define O_WD     20736                // Wd [64][72]               = 4608
#define O_P(p)   (25344 + (p) * 3840) // A^T chunk [32 k][120]     = 3840 x2
#define O_AY     25344                // AY [112][68] overlay      = 7616
#define O_BT     33024                // bt [64]
#define O_BD     33088                // bd [64]
#define SMP_FLT  33152
#define SMEM_PERS (SMP_FLT * 4)       // 132608 bytes

// ---------------- init ----------------
__global__ void __launch_bounds__(512) k_init(const float* __restrict__ x,
                                              const float* __restrict__ A) {
    int gid = blockIdx.x * blockDim.x + threadIdx.x;
    int stride = gridDim.x * blockDim.x;
    for (int idx = gid; idx < KPAD * BH; idx += stride) {
        int n = idx >> 12, c = idx & 4095;
        float v = 0.0f;
        if (n < NODES) {
            int b = c >> 6, h = c & 63;
            v = x[b * ROW + n * HID + h];
        }
        g_yA[idx] = v;
    }
    for (int idx = gid; idx < KPAD * MPAD; idx += stride) {
        int k = idx >> 8, m = idx & 255;
        g_ApadT[idx] = (m < NODES && k < NODES) ? A[m * NODES + k] : 0.0f;
    }
    if (gid < 100) {
        unsigned o0, o1;
        tf2x32(0u, 42u, 0u, (unsigned)gid, o0, o1);
        g_flat[2 * gid]     = o0;
        g_flat[2 * gid + 1] = o1;
    }
}

// ---------------- persistent SDE kernel ----------------
// grid 128, cluster 2 (pair = one batch). 224 threads = 7 warps; warp w owns m-tile w.
__global__ void __launch_bounds__(224, 1) k_pers(
        const float* __restrict__ Wt, const float* __restrict__ bt,
        const float* __restrict__ Wd, const float* __restrict__ bd) {
    extern __shared__ float sm[];
    int tid = threadIdx.x, lane = tid & 31, w = tid >> 5;
    int batch = blockIdx.x >> 1;
    int rank  = blockIdx.x & 1;
    int mbase = rank * MHALF;          // global node base of my half
    int n0    = batch << 6;            // bh col base
    int g = lane >> 2, tg = lane & 3;
    uint32_t smb = smem_u32(sm);
    uint32_t ybase = smb + O_Y * 4;
    uint32_t ybase_peer;
    asm("mapa.shared::cluster.u32 %0, %1, %2;"
        : "=r"(ybase_peer) : "r"(ybase), "r"(rank ^ 1));

    // ---- one-time loads: y (full), W tiles, biases ----
    for (int i = tid; i < KPAD * HID; i += 224) {
        int node = i >> 6, h = i & 63;
        sm[O_Y + node * 72 + h] = g_yA[node * BH + n0 + h];
    }
    for (int i = tid; i < 4096; i += 224) {
        int r = i >> 6, c = i & 63;
        sm[O_WT + r * 72 + c] = __ldg(&Wt[i]);
        sm[O_WD + r * 72 + c] = __ldg(&Wd[i]);
    }
    if (tid < 64) {
        sm[O_BT + tid] = __ldg(&bt[tid]);
        sm[O_BD + tid] = __ldg(&bd[tid]);
    }
    __syncthreads();

#define STAGE(c, p) do { \
    _Pragma("unroll") \
    for (int i_ = 0; i_ < 4; i_++) { \
        int t_ = tid + i_ * 224; \
        int r_ = t_ / 28, c4_ = (t_ % 28) << 2; \
        cpa16(smb + (uint32_t)((O_P(p) + r_ * 120 + c4_) << 2), \
              g_ApadT + ((c) * 32 + r_) * 256 + mbase + c4_); \
    } \
} while (0)

    for (int s = 0; s < 100; s++) {
        unsigned key0 = g_flat[2 * s], key1 = g_flat[2 * s + 1];
        STAGE(0, 0); CP_COMMIT();
        STAGE(1, 1); CP_COMMIT();

        // ---- noise for my 32 output elems (overlaps cp.async) ----
        float ns[8][4];
#pragma unroll
        for (int nf = 0; nf < 8; nf++)
#pragma unroll
            for (int q = 0; q < 4; q++) {
                int node = mbase + w * 16 + g + ((q >> 1) << 3);
                int h = (nf << 3) + (tg << 1) + (q & 1);
                ns[nf][q] = (node < NODES)
                    ? bits_to_normal(tf_bits32(key0, key1,
                          (unsigned)(batch * ROW + node * HID + h)))
                    : 0.0f;
            }

        // ---- A@Y for my half: m-tile w (16 rows), n = 64, k = 224 ----
        float acc[8][4];
#pragma unroll
        for (int nf = 0; nf < 8; nf++)
#pragma unroll
            for (int q = 0; q < 4; q++) acc[nf][q] = 0.0f;

        for (int c = 0; c < 7; c++) {
            int p = c & 1;
            if (c < 6) CP_WAIT1(); else CP_WAIT0();
            __syncthreads();
            const float* bufA = sm + O_P(p);
#pragma unroll
            for (int kk = 0; kk < 4; kk++) {
                int kb = kk << 3;
                uint32_t a[4];
                a[0] = __float_as_uint(bufA[(kb + tg) * 120 + w * 16 + g]);
                a[1] = __float_as_uint(bufA[(kb + tg) * 120 + w * 16 + g + 8]);
                a[2] = __float_as_uint(bufA[(kb + tg + 4) * 120 + w * 16 + g]);
                a[3] = __float_as_uint(bufA[(kb + tg + 4) * 120 + w * 16 + g + 8]);
                int krow = c * 32 + kb;
#pragma unroll
                for (int nf = 0; nf < 8; nf++) {
                    int cn = (nf << 3) + g;
                    uint32_t b2[2];
                    b2[0] = __float_as_uint(sm[O_Y + (krow + tg) * 72 + cn]);
                    b2[1] = __float_as_uint(sm[O_Y + (krow + tg + 4) * 72 + cn]);
                    MMA_TF32(acc[nf], a, b2);
                }
            }
            __syncthreads();
            if (c + 2 <= 6) { STAGE(c + 2, p); CP_COMMIT(); }
        }

        // ---- AY -> smem scratch (overlays A pipe bufs; all cp.async drained) ----
#pragma unroll
        for (int nf = 0; nf < 8; nf++) {
            int lr = w * 16 + g;
            int cc = (nf << 3) + (tg << 1);
            *(float2*)&sm[O_AY + lr * 68 + cc] = make_float2(acc[nf][0], acc[nf][1]);
            *(float2*)&sm[O_AY + (lr + 8) * 68 + cc] = make_float2(acc[nf][2], acc[nf][3]);
        }
        __syncthreads();

        // ---- heads: AY[16x64] @ Wt/Wd[64x64] ----
        float aT[8][4], aD[8][4];
#pragma unroll
        for (int nf = 0; nf < 8; nf++)
#pragma unroll
            for (int q = 0; q < 4; q++) { aT[nf][q] = 0.0f; aD[nf][q] = 0.0f; }
#pragma unroll
        for (int kk = 0; kk < 8; kk++) {
            int kb = kk << 3;
            uint32_t a2[4];
            a2[0] = __float_as_uint(sm[O_AY + (w * 16 + g) * 68 + kb + tg]);
            a2[1] = __float_as_uint(sm[O_AY + (w * 16 + g + 8) * 68 + kb + tg]);
            a2[2] = __float_as_uint(sm[O_AY + (w * 16 + g) * 68 + kb + tg + 4]);
            a2[3] = __float_as_uint(sm[O_AY + (w * 16 + g + 8) * 68 + kb + tg + 4]);
#pragma unroll
            for (int nf = 0; nf < 8; nf++) {
                int cn = (nf << 3) + g;
                uint32_t b2t[2], b2d[2];
                b2t[0] = __float_as_uint(sm[O_WT + (kb + tg) * 72 + cn]);
                b2t[1] = __float_as_uint(sm[O_WT + (kb + tg + 4) * 72 + cn]);
                b2d[0] = __float_as_uint(sm[O_WD + (kb + tg) * 72 + cn]);
                b2d[1] = __float_as_uint(sm[O_WD + (kb + tg + 4) * 72 + cn]);
                MMA_TF32(aT[nf], a2, b2t);
                MMA_TF32(aD[nf], a2, b2d);
            }
        }

        // ---- barrier #1: all y reads (both CTAs) complete before any y writes ----
        CLUSTER_SYNC();

        // ---- EM update: write own smem + peer smem (DSMEM) ----
#pragma unroll
        for (int nf = 0; nf < 8; nf++) {
            int cc = (nf << 3) + (tg << 1);
            float2 btv = *(const float2*)&sm[O_BT + cc];
            float2 bdv = *(const float2*)&sm[O_BD + cc];
#pragma unroll
            for (int half = 0; half < 2; half++) {
                int node = mbase + w * 16 + g + half * 8;
                if (node < NODES) {
                    int qb = half << 1;
                    uint32_t off = (uint32_t)((O_Y + node * 72 + cc) << 2) - (uint32_t)(O_Y << 2);
                    float2 yp = *(const float2*)&sm[O_Y + node * 72 + cc];
                    float2 o;
                    o.x = yp.x + 0.001f * tanhf(aT[nf][qb] + btv.x)
                               + 0.01f * tanhf(aD[nf][qb] + bdv.x) * ns[nf][qb];
                    o.y = yp.y + 0.001f * tanhf(aT[nf][qb + 1] + btv.y)
                               + 0.01f * tanhf(aD[nf][qb + 1] + bdv.y) * ns[nf][qb + 1];
                    *(float2*)&sm[O_Y + node * 72 + cc] = o;
                    unsigned long long pk =
                        ((unsigned long long)__float_as_uint(o.y) << 32) | __float_as_uint(o.x);
                    asm volatile("st.shared::cluster.b64 [%0], %1;"
                                 :: "r"(ybase_peer + off), "l"(pk) : "memory");
                }
            }
        }

        // ---- barrier #2: all writes visible before next step's reads ----
        CLUSTER_SYNC();
    }

    // ---- write back my half of final y ----
    for (int i = tid; i < MHALF * HID; i += 224) {
        int ml = i >> 6, h = i & 63;
        int node = mbase + ml;
        if (node < NODES)
            g_yA[node * BH + n0 + h] = sm[O_Y + node * 72 + h];
    }
#undef STAGE
}

// ---------------- output head: 3xTF32 tensor MMA ----------------
#define OY 0
#define OW 4608
#define SMO ((4608 + 16640) * 4)
__global__ void __launch_bounds__(256, 2) k_out(const float* __restrict__ Wo,
                                                const float* __restrict__ bo,
                                                float* __restrict__ out) {
    extern __shared__ float so[];
    int n  = blockIdx.y;
    int c0 = blockIdx.x << 8;
    int tid = threadIdx.x, lane = tid & 31, wid = tid >> 5;
    int wm = (wid >> 2) << 5;
    int wn = (wid & 3) << 6;
    int g = lane >> 2, tg = lane & 3;

#pragma unroll
    for (int i = 0; i < 4; i++) {
        int t = tid + (i << 8);
        int b = t >> 4, k4 = (t & 15) << 2;
        *(float4*)&so[OY + b * 72 + k4] = __ldg((const float4*)&g_yA[n * BH + b * 64 + k4]);
    }
#pragma unroll
    for (int i = 0; i < 16; i++) {
        int t = tid + (i << 8);
        int k = t >> 6, c4 = (t & 63) << 2;
        *(float4*)&so[OW + k * 260 + c4] = __ldg((const float4*)&Wo[k * BH + c0 + c4]);
    }
    __syncthreads();

    float acc[2][8][4];
#pragma unroll
    for (int mi = 0; mi < 2; mi++)
#pragma unroll
        for (int ni = 0; ni < 8; ni++)
#pragma unroll
            for (int q = 0; q < 4; q++) acc[mi][ni][q] = 0.0f;

#pragma unroll
    for (int kk = 0; kk < 8; kk++) {
        int kb = kk << 3;
        uint32_t ah[2][4], al[2][4];
#pragma unroll
        for (int mi = 0; mi < 2; mi++) {
            int rm = wm + (mi << 4) + g;
#pragma unroll
            for (int q = 0; q < 4; q++) {
                float v = so[OY + (rm + ((q & 1) << 3)) * 72 + kb + tg + ((q >> 1) << 2)];
                float h = tf32r(v);
                ah[mi][q] = __float_as_uint(h);
                al[mi][q] = __float_as_uint(tf32r(v - h));
            }
        }
#pragma unroll
        for (int ni = 0; ni < 8; ni++) {
            int cn = wn + (ni << 3) + g;
            float v0 = so[OW + (kb + tg) * 260 + cn];
            float v1 = so[OW + (kb + tg + 4) * 260 + cn];
            float h0 = tf32r(v0), h1 = tf32r(v1);
            uint32_t bh2[2] = {__float_as_uint(h0), __float_as_uint(h1)};
            uint32_t bl2[2] = {__float_as_uint(tf32r(v0 - h0)), __float_as_uint(tf32r(v1 - h1))};
#pragma unroll
            for (int mi = 0; mi < 2; mi++) {
                MMA_TF32(acc[mi][ni], ah[mi], bh2);
                MMA_TF32(acc[mi][ni], al[mi], bh2);
                MMA_TF32(acc[mi][ni], ah[mi], bl2);
            }
        }
    }

#pragma unroll
    for (int ni = 0; ni < 8; ni++) {
        int col = c0 + wn + (ni << 3) + (tg << 1);
        float2 bov = __ldg((const float2*)&bo[col]);
#pragma unroll
        for (int mi = 0; mi < 2; mi++) {
            int b0 = wm + (mi << 4) + g;
            float2 o0, o1;
            o0.x = tanhf(acc[mi][ni][0] + bov.x);
            o0.y = tanhf(acc[mi][ni][1] + bov.y);
            o1.x = tanhf(acc[mi][ni][2] + bov.x);
            o1.y = tanhf(acc[mi][ni][3] + bov.y);
            *(float2*)&out[(b0 * NODES + n) * 4096 + col] = o0;
            *(float2*)&out[((b0 + 8) * NODES + n) * 4096 + col] = o1;
        }
    }
}

// ---------------- host ----------------
extern "C" void kernel_launch(void* const* d_in, const int* in_sizes, int n_in,
                              void* d_out, int out_size) {
    const float* x  = (const float*)d_in[0];
    const float* A  = (const float*)d_in[1];
    const float* Wt = (const float*)d_in[2];
    const float* bt = (const float*)d_in[3];
    const float* Wd = (const float*)d_in[4];
    const float* bd = (const float*)d_in[5];
    const float* Wo = (const float*)d_in[6];
    const float* bo = (const float*)d_in[7];
    float* out = (float*)d_out;

    cudaFuncSetAttribute(k_pers, cudaFuncAttributeMaxDynamicSharedMemorySize, SMEM_PERS);
    cudaFuncSetAttribute(k_out, cudaFuncAttributeMaxDynamicSharedMemorySize, SMO);

    k_init<<<416, 512>>>(x, A);

    cudaLaunchConfig_t cfg = {};
    cfg.gridDim = dim3(128, 1, 1);
    cfg.blockDim = dim3(224, 1, 1);
    cfg.dynamicSmemBytes = SMEM_PERS;
    cudaLaunchAttribute attrs[1];
    attrs[0].id = cudaLaunchAttributeClusterDimension;
    attrs[0].val.clusterDim = {2, 1, 1};
    cfg.attrs = attrs;
    cfg.numAttrs = 1;
    cudaLaunchKernelEx(&cfg, k_pers, Wt, bt, Wd, bd);

    k_out<<<dim3(16, 207), 256, SMO>>>(Wo, bo, out);
}

// round 15
// speedup vs baseline: 1.0838x; 1.0838x over previous
#include <cuda_runtime.h>
#include <cuda_bf16.h>
#include <cstdint>

#define NODES 207
#define HID   64
#define BATCH 64
#define BH    4096          // BATCH*HID
#define ROW   13248         // NODES*HID
#define KPAD  224           // node dim padded (7 chunks of 32)
#define KPH   112           // kpairs (KPAD/2)
#define MPAD  256
#define NSTRIDE (KPAD * BH) // per-step noise stride

// ---------------- device state ----------------
__device__ float g_yA[KPAD * BH];          // y ping (fp32 master) [node][bh]
__device__ float g_yB[KPAD * BH];          // y pong
__device__ uint32_t g_AbfT[KPH * MPAD];    // A^T bf16-packed [kpair][m]
__device__ uint32_t g_ybf[2][KPH * BH];    // y bf16-packed mirrors [kpair][bh]
__device__ float g_noise[10 * NSTRIDE];    // 10-step noise group [s10][node][bh]
__device__ unsigned g_flat[256];           // per-step keys

// ---------------- threefry (partitionable) ----------------
__device__ __forceinline__ void tf2x32(unsigned k0, unsigned k1,
                                       unsigned x0, unsigned x1,
                                       unsigned &o0, unsigned &o1) {
    unsigned ks2 = k0 ^ k1 ^ 0x1BD11BDAu;
    x0 += k0; x1 += k1;
#define TFR(r) { x0 += x1; x1 = __funnelshift_l(x1, x1, (r)); x1 ^= x0; }
    TFR(13) TFR(15) TFR(26) TFR(6)
    x0 += k1;  x1 += ks2 + 1u;
    TFR(17) TFR(29) TFR(16) TFR(24)
    x0 += ks2; x1 += k0 + 2u;
    TFR(13) TFR(15) TFR(26) TFR(6)
    x0 += k0;  x1 += k1 + 3u;
    TFR(17) TFR(29) TFR(16) TFR(24)
    x0 += k1;  x1 += ks2 + 4u;
    TFR(13) TFR(15) TFR(26) TFR(6)
    x0 += ks2; x1 += k0 + 5u;
#undef TFR
    o0 = x0; o1 = x1;
}
__device__ __forceinline__ unsigned tf_bits32(unsigned k0, unsigned k1, unsigned i) {
    unsigned o0, o1;
    tf2x32(k0, k1, 0u, i, o0, o1);
    return o0 ^ o1;
}
__device__ __forceinline__ float bits_to_normal(unsigned b) {
    float f = __uint_as_float((b >> 9) | 0x3F800000u) - 1.0f;
    float u = fmaf(f, 2.0f, -0.99999994f);
    u = fmaxf(u, -0.99999994f);
    return 1.41421356f * erfinvf(u);
}

// ---------------- helpers ----------------
__device__ __forceinline__ uint32_t smem_u32(const void* p) {
    uint32_t a;
    asm("{ .reg .u64 t; cvta.to.shared.u64 t, %1; cvt.u32.u64 %0, t; }" : "=r"(a) : "l"(p));
    return a;
}
__device__ __forceinline__ void cpa16(uint32_t s, const void* g) {
    asm volatile("{ .reg .u64 ga; cvta.to.global.u64 ga, %1; "
                 "cp.async.cg.shared.global [%0], [ga], 16; }"
                 :: "r"(s), "l"(g));
}
#define CP_COMMIT() asm volatile("cp.async.commit_group;" ::: "memory")
#define CP_WAIT1()  asm volatile("cp.async.wait_group 1;" ::: "memory")
#define CP_WAIT0()  asm volatile("cp.async.wait_group 0;" ::: "memory")

__device__ __forceinline__ uint32_t packbf(float lo, float hi) {
    __nv_bfloat162 t = __floats2bfloat162_rn(lo, hi);
    return *reinterpret_cast<uint32_t*>(&t);
}
__device__ __forceinline__ float tf32r(float x) {
    uint32_t r;
    asm("cvt.rna.tf32.f32 %0, %1;" : "=r"(r) : "f"(x));
    return __uint_as_float(r);
}
#define MMA_TF32(acc, a, b) \
    asm volatile("mma.sync.aligned.m16n8k8.row.col.f32.tf32.tf32.f32 " \
        "{%0,%1,%2,%3}, {%4,%5,%6,%7}, {%8,%9}, {%0,%1,%2,%3};" \
        : "+f"((acc)[0]), "+f"((acc)[1]), "+f"((acc)[2]), "+f"((acc)[3]) \
        : "r"((a)[0]), "r"((a)[1]), "r"((a)[2]), "r"((a)[3]), \
          "r"((b)[0]), "r"((b)[1]))
#define MMA_BF16(acc, a, b) \
    asm volatile("mma.sync.aligned.m16n8k16.row.col.f32.bf16.bf16.f32 " \
        "{%0,%1,%2,%3}, {%4,%5,%6,%7}, {%8,%9}, {%0,%1,%2,%3};" \
        : "+f"((acc)[0]), "+f"((acc)[1]), "+f"((acc)[2]), "+f"((acc)[3]) \
        : "r"((a)[0]), "r"((a)[1]), "r"((a)[2]), "r"((a)[3]), \
          "r"((b)[0]), "r"((b)[1]))

// k_fused dynamic smem layout (4B words)
#define O_PA(p)  ((p) * 1152)             // A bf16 chunk [16 kp][72] u32
#define O_PB(p)  (2304 + (p) * 1152)      // y bf16 chunk [16 kp][72] u32
#define O_WT     4608                     // Wt fp32 [64][72]
#define O_WD     9216                     // Wd fp32 [64][72]
#define O_AY     0                        // AY / new-y fp32 [64][68] overlay
#define SMF_W    13824
#define SMEM_FUSED (SMF_W * 4)            // 55296 bytes

// ---------------- init ----------------
__global__ void __launch_bounds__(512) k_init(const float* __restrict__ x,
                                              const float* __restrict__ A) {
    int gid = blockIdx.x * blockDim.x + threadIdx.x;
    int stride = gridDim.x * blockDim.x;
    for (int idx = gid; idx < KPAD * BH; idx += stride) {
        int n = idx >> 12, c = idx & 4095;
        float v = 0.0f;
        if (n < NODES) {
            int b = c >> 6, h = c & 63;
            v = x[b * ROW + n * HID + h];
        }
        g_yA[idx] = v;
        g_yB[idx] = 0.0f;
    }
    // A^T bf16-packed: [kpair][m], lo = k even
    for (int idx = gid; idx < KPH * MPAD; idx += stride) {
        int kp = idx >> 8, m = idx & 255;
        int k0 = 2 * kp, k1 = 2 * kp + 1;
        float a0 = (m < NODES && k0 < NODES) ? A[m * NODES + k0] : 0.0f;
        float a1 = (m < NODES && k1 < NODES) ? A[m * NODES + k1] : 0.0f;
        g_AbfT[idx] = packbf(a0, a1);
    }
    // y bf16 mirror (parity 0) from x
    for (int idx = gid; idx < KPH * BH; idx += stride) {
        int kp = idx >> 12, bh = idx & 4095;
        int b = bh >> 6, h = bh & 63;
        int n0 = 2 * kp, n1 = 2 * kp + 1;
        float y0 = (n0 < NODES) ? x[b * ROW + n0 * HID + h] : 0.0f;
        float y1 = (n1 < NODES) ? x[b * ROW + n1 * HID + h] : 0.0f;
        g_ybf[0][idx] = packbf(y0, y1);
        g_ybf[1][idx] = 0u;
    }
    if (gid < 100) {
        unsigned o0, o1;
        tf2x32(0u, 42u, 0u, (unsigned)gid, o0, o1);
        g_flat[2 * gid]     = o0;
        g_flat[2 * gid + 1] = o1;
    }
}

// ---------------- noise precompute: 10 steps per launch ----------------
__global__ void __launch_bounds__(512) k_noise(int s_base) {
    int v = (blockIdx.x * 512 + threadIdx.x) * 4;
    if (v >= 10 * NODES * 4096) return;
    int s10 = v / (NODES * 4096);
    int rem = v - s10 * (NODES * 4096);
    int node = rem >> 12;
    int bh = v & 4095;
    int b = bh >> 6, h = bh & 63;
    unsigned key0 = g_flat[2 * (s_base + s10)];
    unsigned key1 = g_flat[2 * (s_base + s10) + 1];
    unsigned base = (unsigned)(b * ROW + node * HID + h);
    float4 r;
    r.x = bits_to_normal(tf_bits32(key0, key1, base));
    r.y = bits_to_normal(tf_bits32(key0, key1, base + 1u));
    r.z = bits_to_normal(tf_bits32(key0, key1, base + 2u));
    r.w = bits_to_normal(tf_bits32(key0, key1, base + 3u));
    *(float4*)&g_noise[s10 * NSTRIDE + node * 4096 + bh] = r;
}

// ---------------- fused step: bf16 A@Y + tf32 heads + EM update ----------------
// grid (64 batches, 4 m-tiles of 64) x 256 threads
__global__ void __launch_bounds__(256) k_fused(int s,
        const float* __restrict__ Wt, const float* __restrict__ bt,
        const float* __restrict__ Wd, const float* __restrict__ bd) {
    extern __shared__ float sm[];
    uint32_t* usm = (uint32_t*)sm;
    const float* yR = (s & 1) ? g_yB : g_yA;
    float*       yW = (s & 1) ? g_yA : g_yB;
    const uint32_t* ybR = g_ybf[s & 1];
    uint32_t*       ybW = g_ybf[(s & 1) ^ 1];
    int tid = threadIdx.x, lane = tid & 31, wid = tid >> 5;
    int bx = blockIdx.x;
    int n0 = bx << 6;
    int m0 = blockIdx.y << 6;
    int wm = (wid >> 2) << 5;      // 0,32
    int wn = (wid & 3) << 4;       // 0,16,32,48
    int g = lane >> 2, tg = lane & 3;
    uint32_t smb = smem_u32(sm);

#define STAGE_CHUNK(c, p) do { \
    _Pragma("unroll") \
    for (int i_ = 0; i_ < 2; i_++) { \
        int t_ = tid + (i_ << 8); \
        int r_ = (t_ >> 4) & 15, seg_ = t_ & 15; \
        if (t_ < 256) \
            cpa16(smb + (uint32_t)((O_PA(p) + r_ * 72 + seg_ * 4) << 2), \
                  g_AbfT + ((c) * 16 + r_) * 256 + m0 + seg_ * 4); \
        else \
            cpa16(smb + (uint32_t)((O_PB(p) + r_ * 72 + seg_ * 4) << 2), \
                  ybR + ((c) * 16 + r_) * 4096 + n0 + seg_ * 4); \
    } \
} while (0)

    // prologue: W tiles + chunk0 (group 0), chunk1 (group 1)
#pragma unroll
    for (int i = 0; i < 8; i++) {
        int t = tid + (i << 8);
        int wsel = t >> 10, r = (t >> 4) & 63, seg = t & 15;
        const float* src = wsel ? Wd : Wt;
        int dst = (wsel ? O_WD : O_WT) + r * 72 + seg * 4;
        cpa16(smb + (uint32_t)(dst << 2), src + r * 64 + seg * 4);
    }
    STAGE_CHUNK(0, 0);
    CP_COMMIT();
    STAGE_CHUNK(1, 1);
    CP_COMMIT();

    // ---- main loop: A@Y bf16, k = 224 over 7 chunks x 2 k16 ----
    float acc[2][2][4];
#pragma unroll
    for (int mi = 0; mi < 2; mi++)
#pragma unroll
        for (int ni = 0; ni < 2; ni++)
#pragma unroll
            for (int q = 0; q < 4; q++) acc[mi][ni][q] = 0.0f;

    for (int c = 0; c < 7; c++) {
        int p = c & 1;
        if (c < 6) CP_WAIT1(); else CP_WAIT0();
        __syncthreads();
        const uint32_t* bufA = usm + O_PA(p);
        const uint32_t* bufB = usm + O_PB(p);
#pragma unroll
        for (int kk = 0; kk < 2; kk++) {
            int kpb = kk << 3;
            uint32_t a[2][4], b[2][2];
#pragma unroll
            for (int mi = 0; mi < 2; mi++) {
                int rm = wm + (mi << 4) + g;
                a[mi][0] = bufA[(kpb + tg) * 72 + rm];
                a[mi][1] = bufA[(kpb + tg) * 72 + rm + 8];
                a[mi][2] = bufA[(kpb + tg + 4) * 72 + rm];
                a[mi][3] = bufA[(kpb + tg + 4) * 72 + rm + 8];
            }
#pragma unroll
            for (int ni = 0; ni < 2; ni++) {
                int cn = wn + (ni << 3) + g;
                b[ni][0] = bufB[(kpb + tg) * 72 + cn];
                b[ni][1] = bufB[(kpb + tg + 4) * 72 + cn];
            }
#pragma unroll
            for (int mi = 0; mi < 2; mi++)
#pragma unroll
                for (int ni = 0; ni < 2; ni++)
                    MMA_BF16(acc[mi][ni], a[mi], b[ni]);
        }
        __syncthreads();
        if (c + 2 <= 6) { STAGE_CHUNK(c + 2, p); CP_COMMIT(); }
    }

    // ---- AY -> smem [64][68] (overlays pipe buffers) ----
    __syncthreads();
#pragma unroll
    for (int mi = 0; mi < 2; mi++)
#pragma unroll
        for (int ni = 0; ni < 2; ni++) {
            int lr = wm + (mi << 4) + g;
            int cc = wn + (ni << 3) + (tg << 1);
            *(float2*)&sm[O_AY + lr * 68 + cc] = make_float2(acc[mi][ni][0], acc[mi][ni][1]);
            *(float2*)&sm[O_AY + (lr + 8) * 68 + cc] = make_float2(acc[mi][ni][2], acc[mi][ni][3]);
        }
    __syncthreads();

    // ---- heads (tf32): AY[64x64] @ Wt/Wd[64x64] ----
    float aT[2][2][4], aD[2][2][4];
#pragma unroll
    for (int mi = 0; mi < 2; mi++)
#pragma unroll
        for (int ni = 0; ni < 2; ni++)
#pragma unroll
            for (int q = 0; q < 4; q++) { aT[mi][ni][q] = 0.0f; aD[mi][ni][q] = 0.0f; }
#pragma unroll
    for (int kk = 0; kk < 8; kk++) {
        int kb = kk << 3;
        uint32_t a2[2][4];
#pragma unroll
        for (int mi = 0; mi < 2; mi++) {
            int rm = wm + (mi << 4) + g;
            a2[mi][0] = __float_as_uint(sm[O_AY + rm * 68 + kb + tg]);
            a2[mi][1] = __float_as_uint(sm[O_AY + (rm + 8) * 68 + kb + tg]);
            a2[mi][2] = __float_as_uint(sm[O_AY + rm * 68 + kb + tg + 4]);
            a2[mi][3] = __float_as_uint(sm[O_AY + (rm + 8) * 68 + kb + tg + 4]);
        }
#pragma unroll
        for (int ni = 0; ni < 2; ni++) {
            int cn = wn + (ni << 3) + g;
            uint32_t b2t[2], b2d[2];
            b2t[0] = __float_as_uint(sm[O_WT + (kb + tg) * 72 + cn]);
            b2t[1] = __float_as_uint(sm[O_WT + (kb + tg + 4) * 72 + cn]);
            b2d[0] = __float_as_uint(sm[O_WD + (kb + tg) * 72 + cn]);
            b2d[1] = __float_as_uint(sm[O_WD + (kb + tg + 4) * 72 + cn]);
#pragma unroll
            for (int mi = 0; mi < 2; mi++) {
                MMA_TF32(aT[mi][ni], a2[mi], b2t);
                MMA_TF32(aD[mi][ni], a2[mi], b2d);
            }
        }
    }
    __syncthreads();   // all AY reads done; safe to overwrite with new-y

    // ---- EM update: y_next = y + 0.001*tanh(T+bt) + 0.01*tanh(D+bd)*noise ----
    const float* nsbase = g_noise + (s % 10) * NSTRIDE;
#pragma unroll
    for (int mi = 0; mi < 2; mi++)
#pragma unroll
        for (int ni = 0; ni < 2; ni++) {
            int cc = wn + (ni << 3) + (tg << 1);
            float2 btv = __ldg((const float2*)&bt[cc]);
            float2 bdv = __ldg((const float2*)&bd[cc]);
#pragma unroll
            for (int half = 0; half < 2; half++) {
                int lrow = wm + (mi << 4) + g + (half << 3);
                int node = m0 + lrow;
                int qb = half << 1;
                float2 o;
                if (node < NODES) {
                    float2 yp = *(const float2*)&yR[node * BH + n0 + cc];
                    float2 nv = *(const float2*)&nsbase[node * 4096 + n0 + cc];
                    o.x = yp.x + 0.001f * tanhf(aT[mi][ni][qb] + btv.x)
                               + 0.01f * tanhf(aD[mi][ni][qb] + bdv.x) * nv.x;
                    o.y = yp.y + 0.001f * tanhf(aT[mi][ni][qb + 1] + btv.y)
                               + 0.01f * tanhf(aD[mi][ni][qb + 1] + bdv.y) * nv.y;
                    *(float2*)&yW[node * BH + n0 + cc] = o;
                } else {
                    o.x = 0.0f; o.y = 0.0f;
                }
                *(float2*)&sm[O_AY + lrow * 68 + cc] = o;
            }
        }
    __syncthreads();

    // ---- repack new-y tile to bf16 mirror ----
#pragma unroll
    for (int i = 0; i < 8; i++) {
        int idx = tid + (i << 8);
        int kp_l = idx >> 6, h = idx & 63;
        int kpg = (m0 >> 1) + kp_l;
        if (kpg < KPH) {
            float lo = sm[O_AY + (2 * kp_l) * 68 + h];
            float hi = sm[O_AY + (2 * kp_l + 1) * 68 + h];
            ybW[kpg * 4096 + n0 + h] = packbf(lo, hi);
        }
    }
#undef STAGE_CHUNK
}

// ---------------- output head: 3xTF32 tensor MMA ----------------
#define OY 0
#define OW 4608
#define SMO ((4608 + 16640) * 4)
__global__ void __launch_bounds__(256, 2) k_out(const float* __restrict__ Wo,
                                                const float* __restrict__ bo,
                                                float* __restrict__ out) {
    extern __shared__ float so[];
    int n  = blockIdx.y;
    int c0 = blockIdx.x << 8;
    int tid = threadIdx.x, lane = tid & 31, wid = tid >> 5;
    int wm = (wid >> 2) << 5;
    int wn = (wid & 3) << 6;
    int g = lane >> 2, tg = lane & 3;

#pragma unroll
    for (int i = 0; i < 4; i++) {
        int t = tid + (i << 8);
        int b = t >> 4, k4 = (t & 15) << 2;
        *(float4*)&so[OY + b * 72 + k4] = __ldg((const float4*)&g_yA[n * BH + b * 64 + k4]);
    }
#pragma unroll
    for (int i = 0; i < 16; i++) {
        int t = tid + (i << 8);
        int k = t >> 6, c4 = (t & 63) << 2;
        *(float4*)&so[OW + k * 260 + c4] = __ldg((const float4*)&Wo[k * BH + c0 + c4]);
    }
    __syncthreads();

    float acc[2][8][4];
#pragma unroll
    for (int mi = 0; mi < 2; mi++)
#pragma unroll
        for (int ni = 0; ni < 8; ni++)
#pragma unroll
            for (int q = 0; q < 4; q++) acc[mi][ni][q] = 0.0f;

#pragma unroll
    for (int kk = 0; kk < 8; kk++) {
        int kb = kk << 3;
        uint32_t ah[2][4], al[2][4];
#pragma unroll
        for (int mi = 0; mi < 2; mi++) {
            int rm = wm + (mi << 4) + g;
#pragma unroll
            for (int q = 0; q < 4; q++) {
                float v = so[OY + (rm + ((q & 1) << 3)) * 72 + kb + tg + ((q >> 1) << 2)];
                float h = tf32r(v);
                ah[mi][q] = __float_as_uint(h);
                al[mi][q] = __float_as_uint(tf32r(v - h));
            }
        }
#pragma unroll
        for (int ni = 0; ni < 8; ni++) {
            int cn = wn + (ni << 3) + g;
            float v0 = so[OW + (kb + tg) * 260 + cn];
            float v1 = so[OW + (kb + tg + 4) * 260 + cn];
            float h0 = tf32r(v0), h1 = tf32r(v1);
            uint32_t bh2[2] = {__float_as_uint(h0), __float_as_uint(h1)};
            uint32_t bl2[2] = {__float_as_uint(tf32r(v0 - h0)), __float_as_uint(tf32r(v1 - h1))};
#pragma unroll
            for (int mi = 0; mi < 2; mi++) {
                MMA_TF32(acc[mi][ni], ah[mi], bh2);
                MMA_TF32(acc[mi][ni], al[mi], bh2);
                MMA_TF32(acc[mi][ni], ah[mi], bl2);
            }
        }
    }

#pragma unroll
    for (int ni = 0; ni < 8; ni++) {
        int col = c0 + wn + (ni << 3) + (tg << 1);
        float2 bov = __ldg((const float2*)&bo[col]);
#pragma unroll
        for (int mi = 0; mi < 2; mi++) {
            int b0 = wm + (mi << 4) + g;
            float2 o0, o1;
            o0.x = tanhf(acc[mi][ni][0] + bov.x);
            o0.y = tanhf(acc[mi][ni][1] + bov.y);
            o1.x = tanhf(acc[mi][ni][2] + bov.x);
            o1.y = tanhf(acc[mi][ni][3] + bov.y);
            *(float2*)&out[(b0 * NODES + n) * 4096 + col] = o0;
            *(float2*)&out[((b0 + 8) * NODES + n) * 4096 + col] = o1;
        }
    }
}

// ---------------- host ----------------
extern "C" void kernel_launch(void* const* d_in, const int* in_sizes, int n_in,
                              void* d_out, int out_size) {
    const float* x  = (const float*)d_in[0];
    const float* A  = (const float*)d_in[1];
    const float* Wt = (const float*)d_in[2];
    const float* bt = (const float*)d_in[3];
    const float* Wd = (const float*)d_in[4];
    const float* bd = (const float*)d_in[5];
    const float* Wo = (const float*)d_in[6];
    const float* bo = (const float*)d_in[7];
    float* out = (float*)d_out;

    cudaFuncSetAttribute(k_fused, cudaFuncAttributeMaxDynamicSharedMemorySize, SMEM_FUSED);
    cudaFuncSetAttribute(k_out, cudaFuncAttributeMaxDynamicSharedMemorySize, SMO);

    k_init<<<416, 512>>>(x, A);
    const int nblocks = (10 * NODES * 4096 / 4 + 511) / 512;
    for (int grp = 0; grp < 10; grp++) {
        k_noise<<<nblocks, 512>>>(grp * 10);
        for (int s = grp * 10; s < grp * 10 + 10; s++)
            k_fused<<<dim3(64, 4), 256, SMEM_FUSED>>>(s, Wt, bt, Wd, bd);
    }
    k_out<<<dim3(16, 207), 256, SMO>>>(Wo, bo, out);
}

// round 17
// speedup vs baseline: 1.1616x; 1.0718x over previous
#include <cuda_runtime.h>
#include <cuda_bf16.h>
#include <cstdint>

#define NODES 207
#define HID   64
#define BATCH 64
#define BH    4096          // BATCH*HID
#define ROW   13248         // NODES*HID
#define KPAD  224           // node dim padded (7 chunks of 32)
#define KPH   112           // kpairs (KPAD/2)
#define MPAD  256
#define NSTRIDE (KPAD * BH) // per-step noise stride

// ---------------- device state ----------------
__device__ float g_yA[KPAD * BH];          // y ping (fp32 master) [node][bh]
__device__ float g_yB[KPAD * BH];          // y pong
__device__ uint32_t g_AbfT[KPH * MPAD];    // A^T bf16-packed [kpair][m]
__device__ uint32_t g_ybf[2][KPH * BH];    // y bf16-packed mirrors [kpair][bh]
__device__ float g_noise[10 * NSTRIDE];    // 10-step noise group [s10][node][bh]
__device__ unsigned g_flat[256];           // per-step keys

// ---------------- threefry (partitionable) ----------------
__device__ __forceinline__ void tf2x32(unsigned k0, unsigned k1,
                                       unsigned x0, unsigned x1,
                                       unsigned &o0, unsigned &o1) {
    unsigned ks2 = k0 ^ k1 ^ 0x1BD11BDAu;
    x0 += k0; x1 += k1;
#define TFR(r) { x0 += x1; x1 = __funnelshift_l(x1, x1, (r)); x1 ^= x0; }
    TFR(13) TFR(15) TFR(26) TFR(6)
    x0 += k1;  x1 += ks2 + 1u;
    TFR(17) TFR(29) TFR(16) TFR(24)
    x0 += ks2; x1 += k0 + 2u;
    TFR(13) TFR(15) TFR(26) TFR(6)
    x0 += k0;  x1 += k1 + 3u;
    TFR(17) TFR(29) TFR(16) TFR(24)
    x0 += k1;  x1 += ks2 + 4u;
    TFR(13) TFR(15) TFR(26) TFR(6)
    x0 += ks2; x1 += k0 + 5u;
#undef TFR
    o0 = x0; o1 = x1;
}
__device__ __forceinline__ unsigned tf_bits32(unsigned k0, unsigned k1, unsigned i) {
    unsigned o0, o1;
    tf2x32(k0, k1, 0u, i, o0, o1);
    return o0 ^ o1;
}
__device__ __forceinline__ float bits_to_normal(unsigned b) {
    float f = __uint_as_float((b >> 9) | 0x3F800000u) - 1.0f;
    float u = fmaf(f, 2.0f, -0.99999994f);
    u = fmaxf(u, -0.99999994f);
    return 1.41421356f * erfinvf(u);
}

// ---------------- helpers ----------------
__device__ __forceinline__ uint32_t smem_u32(const void* p) {
    uint32_t a;
    asm("{ .reg .u64 t; cvta.to.shared.u64 t, %1; cvt.u32.u64 %0, t; }" : "=r"(a) : "l"(p));
    return a;
}
__device__ __forceinline__ void cpa16(uint32_t s, const void* g) {
    asm volatile("{ .reg .u64 ga; cvta.to.global.u64 ga, %1; "
                 "cp.async.cg.shared.global [%0], [ga], 16; }"
                 :: "r"(s), "l"(g));
}
#define CP_COMMIT() asm volatile("cp.async.commit_group;" ::: "memory")
#define CP_WAIT2()  asm volatile("cp.async.wait_group 2;" ::: "memory")
#define CP_WAIT1()  asm volatile("cp.async.wait_group 1;" ::: "memory")
#define CP_WAIT0()  asm volatile("cp.async.wait_group 0;" ::: "memory")

__device__ __forceinline__ uint32_t packbf(float lo, float hi) {
    __nv_bfloat162 t = __floats2bfloat162_rn(lo, hi);
    return *reinterpret_cast<uint32_t*>(&t);
}
__device__ __forceinline__ float tf32r(float x) {
    uint32_t r;
    asm("cvt.rna.tf32.f32 %0, %1;" : "=r"(r) : "f"(x));
    return __uint_as_float(r);
}
#define MMA_TF32(acc, a, b) \
    asm volatile("mma.sync.aligned.m16n8k8.row.col.f32.tf32.tf32.f32 " \
        "{%0,%1,%2,%3}, {%4,%5,%6,%7}, {%8,%9}, {%0,%1,%2,%3};" \
        : "+f"((acc)[0]), "+f"((acc)[1]), "+f"((acc)[2]), "+f"((acc)[3]) \
        : "r"((a)[0]), "r"((a)[1]), "r"((a)[2]), "r"((a)[3]), \
          "r"((b)[0]), "r"((b)[1]))
#define MMA_BF16(acc, a, b) \
    asm volatile("mma.sync.aligned.m16n8k16.row.col.f32.bf16.bf16.f32 " \
        "{%0,%1,%2,%3}, {%4,%5,%6,%7}, {%8,%9}, {%0,%1,%2,%3};" \
        : "+f"((acc)[0]), "+f"((acc)[1]), "+f"((acc)[2]), "+f"((acc)[3]) \
        : "r"((a)[0]), "r"((a)[1]), "r"((a)[2]), "r"((a)[3]), \
          "r"((b)[0]), "r"((b)[1]))

// k_fused smem layout (4B words): 4-stage ring; AY overlays PA after mainloop
#define O_PA(p)  ((p) * 640)              // A bf16 chunk [16 kp][40] u32  (x4)
#define O_PB(p)  (2560 + (p) * 1152)      // y bf16 chunk [16 kp][72] u32  (x4)
#define O_WT     7168                     // Wt fp32 [64][72]
#define O_WD     11776                    // Wd fp32 [64][72]
#define O_AY     0                        // AY / new-y fp32 [32][68] overlay
#define SMF_W    16384
#define SMEM_FUSED (SMF_W * 4)            // 65536 bytes -> 3 CTAs/SM

// ---------------- init ----------------
__global__ void __launch_bounds__(512) k_init(const float* __restrict__ x,
                                              const float* __restrict__ A) {
    int gid = blockIdx.x * blockDim.x + threadIdx.x;
    int stride = gridDim.x * blockDim.x;
    for (int idx = gid; idx < KPAD * BH; idx += stride) {
        int n = idx >> 12, c = idx & 4095;
        float v = 0.0f;
        if (n < NODES) {
            int b = c >> 6, h = c & 63;
            v = x[b * ROW + n * HID + h];
        }
        g_yA[idx] = v;
        g_yB[idx] = 0.0f;
    }
    for (int idx = gid; idx < KPH * MPAD; idx += stride) {
        int kp = idx >> 8, m = idx & 255;
        int k0 = 2 * kp, k1 = 2 * kp + 1;
        float a0 = (m < NODES && k0 < NODES) ? A[m * NODES + k0] : 0.0f;
        float a1 = (m < NODES && k1 < NODES) ? A[m * NODES + k1] : 0.0f;
        g_AbfT[idx] = packbf(a0, a1);
    }
    for (int idx = gid; idx < KPH * BH; idx += stride) {
        int kp = idx >> 12, bh = idx & 4095;
        int b = bh >> 6, h = bh & 63;
        int n0 = 2 * kp, n1 = 2 * kp + 1;
        float y0 = (n0 < NODES) ? x[b * ROW + n0 * HID + h] : 0.0f;
        float y1 = (n1 < NODES) ? x[b * ROW + n1 * HID + h] : 0.0f;
        g_ybf[0][idx] = packbf(y0, y1);
        g_ybf[1][idx] = 0u;
    }
    if (gid < 100) {
        unsigned o0, o1;
        tf2x32(0u, 42u, 0u, (unsigned)gid, o0, o1);
        g_flat[2 * gid]     = o0;
        g_flat[2 * gid + 1] = o1;
    }
}

// ---------------- noise precompute: 10 steps per launch ----------------
__global__ void __launch_bounds__(512) k_noise(int s_base) {
    int v = (blockIdx.x * 512 + threadIdx.x) * 4;
    if (v >= 10 * NODES * 4096) return;
    int s10 = v / (NODES * 4096);
    int rem = v - s10 * (NODES * 4096);
    int node = rem >> 12;
    int bh = v & 4095;
    int b = bh >> 6, h = bh & 63;
    unsigned key0 = g_flat[2 * (s_base + s10)];
    unsigned key1 = g_flat[2 * (s_base + s10) + 1];
    unsigned base = (unsigned)(b * ROW + node * HID + h);
    float4 r;
    r.x = bits_to_normal(tf_bits32(key0, key1, base));
    r.y = bits_to_normal(tf_bits32(key0, key1, base + 1u));
    r.z = bits_to_normal(tf_bits32(key0, key1, base + 2u));
    r.w = bits_to_normal(tf_bits32(key0, key1, base + 3u));
    *(float4*)&g_noise[s10 * NSTRIDE + node * 4096 + bh] = r;
}

// ---------------- fused step: bf16 A@Y + tf32 heads + EM update ----------------
// grid (64 batches, 7 m-tiles of 32) x 256 threads; 4-stage cp.async ring
__global__ void __launch_bounds__(256) k_fused(int s,
        const float* __restrict__ Wt, const float* __restrict__ bt,
        const float* __restrict__ Wd, const float* __restrict__ bd) {
    extern __shared__ float sm[];
    uint32_t* usm = (uint32_t*)sm;
    const float* yR = (s & 1) ? g_yB : g_yA;
    float*       yW = (s & 1) ? g_yA : g_yB;
    const uint32_t* ybR = g_ybf[s & 1];
    uint32_t*       ybW = g_ybf[(s & 1) ^ 1];
    int tid = threadIdx.x, lane = tid & 31, wid = tid >> 5;
    int bx = blockIdx.x;
    int n0 = bx << 6;
    int m0 = blockIdx.y << 5;      // node-row base, 0..192
    int wm = (wid >> 2) << 4;      // warp m: 0,16
    int wn = (wid & 3) << 4;       // warp n: 0,16,32,48
    int g = lane >> 2, tg = lane & 3;
    uint32_t smb = smem_u32(sm);

#define STAGE_CHUNK(c, p) do { \
    _Pragma("unroll") \
    for (int i_ = 0; i_ < 2; i_++) { \
        int t_ = tid + (i_ << 8); \
        if (t_ < 128) { \
            int r_ = t_ >> 3, sg_ = t_ & 7; \
            cpa16(smb + (uint32_t)((O_PA(p) + r_ * 40 + sg_ * 4) << 2), \
                  g_AbfT + ((c) * 16 + r_) * 256 + m0 + sg_ * 4); \
        } else if (t_ < 384) { \
            int j_ = t_ - 128; \
            int r_ = j_ >> 4, sg_ = j_ & 15; \
            cpa16(smb + (uint32_t)((O_PB(p) + r_ * 72 + sg_ * 4) << 2), \
                  ybR + ((c) * 16 + r_) * 4096 + n0 + sg_ * 4); \
        } \
    } \
} while (0)

    // prologue: W (group 0 with chunk0) + chunks 0,1,2
#pragma unroll
    for (int i = 0; i < 8; i++) {
        int t = tid + (i << 8);
        int wsel = t >> 10, r = (t >> 4) & 63, seg = t & 15;
        const float* src = wsel ? Wd : Wt;
        int dst = (wsel ? O_WD : O_WT) + r * 72 + seg * 4;
        cpa16(smb + (uint32_t)(dst << 2), src + r * 64 + seg * 4);
    }
    STAGE_CHUNK(0, 0);
    CP_COMMIT();
    STAGE_CHUNK(1, 1);
    CP_COMMIT();
    STAGE_CHUNK(2, 2);
    CP_COMMIT();

    // ---- main loop: A@Y bf16, k=224 over 7 chunks, one sync per iter ----
    float acc[2][4];
#pragma unroll
    for (int ni = 0; ni < 2; ni++)
#pragma unroll
        for (int q = 0; q < 4; q++) acc[ni][q] = 0.0f;

    for (int c = 0; c < 7; c++) {
        int p = c & 3;
        if (c < 5) CP_WAIT2();
        else if (c == 5) CP_WAIT1();
        else CP_WAIT0();
        __syncthreads();   // also proves buffer (c+3)&3 (consumed at iter c-1) is free
        if (c + 3 <= 6) { STAGE_CHUNK(c + 3, (c + 3) & 3); CP_COMMIT(); }
        const uint32_t* bufA = usm + O_PA(p);
        const uint32_t* bufB = usm + O_PB(p);
#pragma unroll
        for (int kk = 0; kk < 2; kk++) {
            int kpb = kk << 3;
            uint32_t a[4], b[2][2];
            a[0] = bufA[(kpb + tg) * 40 + wm + g];
            a[1] = bufA[(kpb + tg) * 40 + wm + g + 8];
            a[2] = bufA[(kpb + tg + 4) * 40 + wm + g];
            a[3] = bufA[(kpb + tg + 4) * 40 + wm + g + 8];
#pragma unroll
            for (int ni = 0; ni < 2; ni++) {
                int cn = wn + (ni << 3) + g;
                b[ni][0] = bufB[(kpb + tg) * 72 + cn];
                b[ni][1] = bufB[(kpb + tg + 4) * 72 + cn];
            }
#pragma unroll
            for (int ni = 0; ni < 2; ni++)
                MMA_BF16(acc[ni], a, b[ni]);
        }
    }

    // ---- AY -> smem [32][68] (overlays PA ring; all loads drained) ----
    __syncthreads();
#pragma unroll
    for (int ni = 0; ni < 2; ni++) {
        int lr = wm + g;
        int cc = wn + (ni << 3) + (tg << 1);
        *(float2*)&sm[O_AY + lr * 68 + cc] = make_float2(acc[ni][0], acc[ni][1]);
        *(float2*)&sm[O_AY + (lr + 8) * 68 + cc] = make_float2(acc[ni][2], acc[ni][3]);
    }
    __syncthreads();

    // ---- heads (tf32): AY[32x64] @ Wt/Wd[64x64] ----
    float aT[2][4], aD[2][4];
#pragma unroll
    for (int ni = 0; ni < 2; ni++)
#pragma unroll
        for (int q = 0; q < 4; q++) { aT[ni][q] = 0.0f; aD[ni][q] = 0.0f; }
#pragma unroll
    for (int kk = 0; kk < 8; kk++) {
        int kb = kk << 3;
        uint32_t a2[4];
        a2[0] = __float_as_uint(sm[O_AY + (wm + g) * 68 + kb + tg]);
        a2[1] = __float_as_uint(sm[O_AY + (wm + g + 8) * 68 + kb + tg]);
        a2[2] = __float_as_uint(sm[O_AY + (wm + g) * 68 + kb + tg + 4]);
        a2[3] = __float_as_uint(sm[O_AY + (wm + g + 8) * 68 + kb + tg + 4]);
#pragma unroll
        for (int ni = 0; ni < 2; ni++) {
            int cn = wn + (ni << 3) + g;
            uint32_t b2t[2], b2d[2];
            b2t[0] = __float_as_uint(sm[O_WT + (kb + tg) * 72 + cn]);
            b2t[1] = __float_as_uint(sm[O_WT + (kb + tg + 4) * 72 + cn]);
            b2d[0] = __float_as_uint(sm[O_WD + (kb + tg) * 72 + cn]);
            b2d[1] = __float_as_uint(sm[O_WD + (kb + tg + 4) * 72 + cn]);
            MMA_TF32(aT[ni], a2, b2t);
            MMA_TF32(aD[ni], a2, b2d);
        }
    }
    __syncthreads();   // all AY reads done; safe to overwrite with new-y

    // ---- EM update ----
    const float* nsbase = g_noise + (s % 10) * NSTRIDE;
#pragma unroll
    for (int ni = 0; ni < 2; ni++) {
        int cc = wn + (ni << 3) + (tg << 1);
        float2 btv = __ldg((const float2*)&bt[cc]);
        float2 bdv = __ldg((const float2*)&bd[cc]);
#pragma unroll
        for (int half = 0; half < 2; half++) {
            int lrow = wm + g + (half << 3);
            int node = m0 + lrow;
            int qb = half << 1;
            float2 o;
            if (node < NODES) {
                float2 yp = *(const float2*)&yR[node * BH + n0 + cc];
                float2 nv = *(const float2*)&nsbase[node * 4096 + n0 + cc];
                o.x = yp.x + 0.001f * tanhf(aT[ni][qb] + btv.x)
                           + 0.01f * tanhf(aD[ni][qb] + bdv.x) * nv.x;
                o.y = yp.y + 0.001f * tanhf(aT[ni][qb + 1] + btv.y)
                           + 0.01f * tanhf(aD[ni][qb + 1] + bdv.y) * nv.y;
                *(float2*)&yW[node * BH + n0 + cc] = o;
            } else {
                o.x = 0.0f; o.y = 0.0f;
            }
            *(float2*)&sm[O_AY + lrow * 68 + cc] = o;
        }
    }
    __syncthreads();

    // ---- repack new-y tile (16 kpairs) to bf16 mirror ----
#pragma unroll
    for (int i = 0; i < 4; i++) {
        int idx = tid + (i << 8);
        int kp_l = idx >> 6, h = idx & 63;
        int kpg = (m0 >> 1) + kp_l;
        float lo = sm[O_AY + (2 * kp_l) * 68 + h];
        float hi = sm[O_AY + (2 * kp_l + 1) * 68 + h];
        ybW[kpg * 4096 + n0 + h] = packbf(lo, hi);
    }
#undef STAGE_CHUNK
}

// ---------------- output head: 3xTF32 tensor MMA ----------------
#define OY 0
#define OW 4608
#define SMO ((4608 + 16640) * 4)
__global__ void __launch_bounds__(256, 2) k_out(const float* __restrict__ Wo,
                                                const float* __restrict__ bo,
                                                float* __restrict__ out) {
    extern __shared__ float so[];
    int n  = blockIdx.y;
    int c0 = blockIdx.x << 8;
    int tid = threadIdx.x, lane = tid & 31, wid = tid >> 5;
    int wm = (wid >> 2) << 5;
    int wn = (wid & 3) << 6;
    int g = lane >> 2, tg = lane & 3;

#pragma unroll
    for (int i = 0; i < 4; i++) {
        int t = tid + (i << 8);
        int b = t >> 4, k4 = (t & 15) << 2;
        *(float4*)&so[OY + b * 72 + k4] = __ldg((const float4*)&g_yA[n * BH + b * 64 + k4]);
    }
#pragma unroll
    for (int i = 0; i < 16; i++) {
        int t = tid + (i << 8);
        int k = t >> 6, c4 = (t & 63) << 2;
        *(float4*)&so[OW + k * 260 + c4] = __ldg((const float4*)&Wo[k * BH + c0 + c4]);
    }
    __syncthreads();

    float acc[2][8][4];
#pragma unroll
    for (int mi = 0; mi < 2; mi++)
#pragma unroll
        for (int ni = 0; ni < 8; ni++)
#pragma unroll
            for (int q = 0; q < 4; q++) acc[mi][ni][q] = 0.0f;

#pragma unroll
    for (int kk = 0; kk < 8; kk++) {
        int kb = kk << 3;
        uint32_t ah[2][4], al[2][4];
#pragma unroll
        for (int mi = 0; mi < 2; mi++) {
            int rm = wm + (mi << 4) + g;
#pragma unroll
            for (int q = 0; q < 4; q++) {
                float v = so[OY + (rm + ((q & 1) << 3)) * 72 + kb + tg + ((q >> 1) << 2)];
                float h = tf32r(v);
                ah[mi][q] = __float_as_uint(h);
                al[mi][q] = __float_as_uint(tf32r(v - h));
            }
        }
#pragma unroll
        for (int ni = 0; ni < 8; ni++) {
            int cn = wn + (ni << 3) + g;
            float v0 = so[OW + (kb + tg) * 260 + cn];
            float v1 = so[OW + (kb + tg + 4) * 260 + cn];
            float h0 = tf32r(v0), h1 = tf32r(v1);
            uint32_t bh2[2] = {__float_as_uint(h0), __float_as_uint(h1)};
            uint32_t bl2[2] = {__float_as_uint(tf32r(v0 - h0)), __float_as_uint(tf32r(v1 - h1))};
#pragma unroll
            for (int mi = 0; mi < 2; mi++) {
                MMA_TF32(acc[mi][ni], ah[mi], bh2);
                MMA_TF32(acc[mi][ni], al[mi], bh2);
                MMA_TF32(acc[mi][ni], ah[mi], bl2);
            }
        }
    }

#pragma unroll
    for (int ni = 0; ni < 8; ni++) {
        int col = c0 + wn + (ni << 3) + (tg << 1);
        float2 bov = __ldg((const float2*)&bo[col]);
#pragma unroll
        for (int mi = 0; mi < 2; mi++) {
            int b0 = wm + (mi << 4) + g;
            float2 o0, o1;
            o0.x = tanhf(acc[mi][ni][0] + bov.x);
            o0.y = tanhf(acc[mi][ni][1] + bov.y);
            o1.x = tanhf(acc[mi][ni][2] + bov.x);
            o1.y = tanhf(acc[mi][ni][3] + bov.y);
            *(float2*)&out[(b0 * NODES + n) * 4096 + col] = o0;
            *(float2*)&out[((b0 + 8) * NODES + n) * 4096 + col] = o1;
        }
    }
}

// ---------------- host ----------------
extern "C" void kernel_launch(void* const* d_in, const int* in_sizes, int n_in,
                              void* d_out, int out_size) {
    const float* x  = (const float*)d_in[0];
    const float* A  = (const float*)d_in[1];
    const float* Wt = (const float*)d_in[2];
    const float* bt = (const float*)d_in[3];
    const float* Wd = (const float*)d_in[4];
    const float* bd = (const float*)d_in[5];
    const float* Wo = (const float*)d_in[6];
    const float* bo = (const float*)d_in[7];
    float* out = (float*)d_out;

    cudaFuncSetAttribute(k_fused, cudaFuncAttributeMaxDynamicSharedMemorySize, SMEM_FUSED);
    cudaFuncSetAttribute(k_out, cudaFuncAttributeMaxDynamicSharedMemorySize, SMO);

    k_init<<<416, 512>>>(x, A);
    const int nblocks = (10 * NODES * 4096 / 4 + 511) / 512;
    for (int grp = 0; grp < 10; grp++) {
        k_noise<<<nblocks, 512>>>(grp * 10);
        for (int s = grp * 10; s < grp * 10 + 10; s++)
            k_fused<<<dim3(64, 7), 256, SMEM_FUSED>>>(s, Wt, bt, Wd, bd);
    }
    k_out<<<dim3(16, 207), 256, SMO>>>(Wo, bo, out);
}